// round 16
// baseline (speedup 1.0000x reference)
#include <cuda_runtime.h>
#include <cuda_bf16.h>
#include <cstdint>

// ---------------- problem constants ----------------
#define B_   8
#define C_   512
#define NPIX 4096          // H*W = 64*64
#define CK   256
#define CV   256
#define CO   512
#define EPS  1e-5f

// ---------------- scratch (device globals; no allocation allowed) ----------
__device__ float g_qk [B_ * CK * NPIX];   // conv-k output, pre-BN   [B,Ck,N]
__device__ float g_vT [B_ * NPIX * CV];   // value transposed        [B,N,Cv]
__device__ float g_ctx[B_ * NPIX * CV];   // attention output        [B,N,Cv]
__device__ float g_mean[CK];
__device__ float g_rstd[CK];

// ---------------- packed f32x2 helpers (FFMA2 path, 2x fp32 rate) ----------
__device__ __forceinline__ unsigned long long f2pack(float lo, float hi) {
    unsigned long long r;
    asm("mov.b64 %0, {%1, %2};" : "=l"(r) : "f"(lo), "f"(hi));
    return r;
}
__device__ __forceinline__ void f2fma(unsigned long long& acc,
                                      unsigned long long a, unsigned long long b) {
    asm("fma.rn.f32x2 %0, %1, %2, %0;" : "+l"(acc) : "l"(a), "l"(b));
}
__device__ __forceinline__ void f2mul(unsigned long long& d, unsigned long long a) {
    asm("mul.rn.f32x2 %0, %0, %1;" : "+l"(d) : "l"(a));
}
__device__ __forceinline__ float2 f2unpack(unsigned long long v) {
    float2 f;
    asm("mov.b64 {%0, %1}, %2;" : "=f"(f.x), "=f"(f.y) : "l"(v));
    return f;
}

// =====================================================================
// Kernel 1: fused QKV 1x1 conv GEMM (f32x2 micro-kernel).
// =====================================================================
#define G_BM 128
#define G_BN 128
#define G_BK 16
#define A_LD 132

__global__ void __launch_bounds__(256) gemm_qkv_kernel(
    const float* __restrict__ x,
    const float* __restrict__ Wk, const float* __restrict__ bk,
    const float* __restrict__ Wv, const float* __restrict__ bv,
    float* __restrict__ value)
{
    __shared__ __align__(16) float As[G_BK][A_LD];
    __shared__ __align__(16) float Bs[G_BK][G_BN];

    const int b  = blockIdx.z;
    const int o0 = blockIdx.y * G_BM;
    const int n0 = blockIdx.x * G_BN;
    const int tid = threadIdx.x;
    const int tx = tid & 15, ty = tid >> 4;

    const bool is_k = (o0 < CK);
    const float* W    = is_k ? Wk : Wv;
    const float* bias = is_k ? bk : bv;
    float*       dst  = is_k ? g_qk : value;
    const int or0 = o0 & (CK - 1);

    unsigned long long acc2[8][4] = {};

    for (int c0 = 0; c0 < C_; c0 += G_BK) {
        #pragma unroll
        for (int r = 0; r < 2; r++) {
            int idx = tid + r * 256;
            int m  = idx >> 2;
            int kq = idx & 3;
            float4 v = *(const float4*)(W + (size_t)(or0 + m) * C_ + c0 + kq * 4);
            As[kq*4+0][m] = v.x; As[kq*4+1][m] = v.y;
            As[kq*4+2][m] = v.z; As[kq*4+3][m] = v.w;
        }
        #pragma unroll
        for (int r = 0; r < 2; r++) {
            int idx = tid + r * 256;
            int k  = idx >> 5;
            int nq = idx & 31;
            *(float4*)&Bs[k][nq*4] =
                *(const float4*)(x + (((size_t)b * C_ + c0 + k) << 12) + n0 + nq * 4);
        }
        __syncthreads();
        #pragma unroll
        for (int k = 0; k < G_BK; k++) {
            float a[8];
            *(float4*)&a[0] = *(float4*)&As[k][ty*8];
            *(float4*)&a[4] = *(float4*)&As[k][ty*8+4];
            ulonglong2 b0 = *(const ulonglong2*)&Bs[k][tx*8];
            ulonglong2 b1 = *(const ulonglong2*)&Bs[k][tx*8+4];
            #pragma unroll
            for (int i = 0; i < 8; i++) {
                unsigned long long ad = f2pack(a[i], a[i]);
                f2fma(acc2[i][0], ad, b0.x);
                f2fma(acc2[i][1], ad, b0.y);
                f2fma(acc2[i][2], ad, b1.x);
                f2fma(acc2[i][3], ad, b1.y);
            }
        }
        __syncthreads();
    }

    #pragma unroll
    for (int i = 0; i < 8; i++) {
        int o = or0 + ty * 8 + i;
        float bi = bias[o];
        float* p = dst + (((size_t)b * CK + o) << 12) + n0 + tx * 8;
        float2 e0 = f2unpack(acc2[i][0]), e1 = f2unpack(acc2[i][1]);
        float2 e2 = f2unpack(acc2[i][2]), e3 = f2unpack(acc2[i][3]);
        float4 v0 = {e0.x+bi, e0.y+bi, e1.x+bi, e1.y+bi};
        float4 v1 = {e2.x+bi, e2.y+bi, e3.x+bi, e3.y+bi};
        *(float4*)p       = v0;
        *(float4*)(p + 4) = v1;
    }
}

// =====================================================================
// Kernel 2: BN training statistics per channel over (B, N) = 32768 vals.
// =====================================================================
__global__ void __launch_bounds__(256) bn_stats_kernel()
{
    const int ck = blockIdx.x;
    float s = 0.f, s2 = 0.f;
    for (int i = threadIdx.x; i < B_ * NPIX; i += 256) {
        int b = i >> 12;
        int n = i & (NPIX - 1);
        float v = g_qk[(((size_t)b * CK + ck) << 12) + n];
        s += v; s2 += v * v;
    }
    #pragma unroll
    for (int off = 16; off > 0; off >>= 1) {
        s  += __shfl_xor_sync(0xffffffffu, s,  off);
        s2 += __shfl_xor_sync(0xffffffffu, s2, off);
    }
    __shared__ float sb[16];
    int w = threadIdx.x >> 5;
    if ((threadIdx.x & 31) == 0) { sb[w] = s; sb[8 + w] = s2; }
    __syncthreads();
    if (threadIdx.x == 0) {
        float S = 0.f, S2 = 0.f;
        #pragma unroll
        for (int i = 0; i < 8; i++) { S += sb[i]; S2 += sb[8 + i]; }
        const float invN = 1.f / (float)(B_ * NPIX);
        float mean = S * invN;
        float var  = S2 * invN - mean * mean;
        g_mean[ck] = mean;
        g_rstd[ck] = rsqrtf(var + EPS);
    }
}

// =====================================================================
// Kernel 3: feat = relu((qk-mean)*rstd*gamma + beta) -> two d_out slots
// =====================================================================
__global__ void __launch_bounds__(256) feat_kernel(
    const float* __restrict__ gamma, const float* __restrict__ beta,
    float* __restrict__ feat1, float* __restrict__ feat2)
{
    int i4 = blockIdx.x * 256 + threadIdx.x;
    int e  = i4 * 4;
    int ck = (e >> 12) & (CK - 1);
    float mu = g_mean[ck], r = g_rstd[ck];
    float sc = r * gamma[ck], be = beta[ck];
    float4 v = *(const float4*)(g_qk + e);
    float4 f;
    f.x = fmaxf(0.f, (v.x - mu) * sc + be);
    f.y = fmaxf(0.f, (v.y - mu) * sc + be);
    f.z = fmaxf(0.f, (v.z - mu) * sc + be);
    f.w = fmaxf(0.f, (v.w - mu) * sc + be);
    *(float4*)(feat1 + e) = f;
    *(float4*)(feat2 + e) = f;
}

// =====================================================================
// Kernel 4: value [B,Cv,N] -> vT [B,N,Cv]  (32x32 smem transpose)
// =====================================================================
__global__ void __launch_bounds__(256) transpose_v_kernel(const float* __restrict__ value)
{
    __shared__ float t[32][33];
    const int b  = blockIdx.z;
    const int n0 = blockIdx.x * 32;
    const int c0 = blockIdx.y * 32;
    #pragma unroll
    for (int r = 0; r < 4; r++) {
        int row = c0 + threadIdx.y + r * 8;
        t[threadIdx.y + r*8][threadIdx.x] =
            value[(((size_t)b * CV + row) << 12) + n0 + threadIdx.x];
    }
    __syncthreads();
    #pragma unroll
    for (int r = 0; r < 4; r++) {
        int row = n0 + threadIdx.y + r * 8;
        g_vT[((size_t)b * NPIX + row) * CV + c0 + threadIdx.x] =
            t[threadIdx.x][threadIdx.y + r*8];
    }
}

// =====================================================================
// Kernel 5: flash attention, fp32 with f32x2 packed FMA inner loops.
//   BM=BN=64, D=256. 256 threads (16x16); each thread: 4x4 of S,
//   4 rows x 16 cols of O (as 8 f32x2 pairs per row).
// =====================================================================
#define PS_LD 65
#define ATTN_SMEM ((16384*3 + 64*PS_LD) * 4)

__global__ void __launch_bounds__(256, 1) attn_kernel(
    const float* __restrict__ feat)   // [B,Ck,N] (d_out feat1 slot)
{
    extern __shared__ __align__(16) float sm[];
    float* Qs = sm;                 // [256][64]  (ck-major, m contiguous)
    float* Ks = sm + 16384;         // [256][64]
    float* Vs = sm + 32768;         // [64][256]  (n-major, cv contiguous)
    float* Ps = sm + 49152;         // [64][PS_LD] transposed: Ps[n][m]

    const int b  = blockIdx.y;
    const int q0 = blockIdx.x * 64;
    const float* f  = feat + (size_t)b * CK * NPIX;
    const float* vt = g_vT + (size_t)b * NPIX * CV;

    const int tid = threadIdx.x;
    const int tx = tid & 15, ty = tid >> 4;
    const int mb = ty * 4, nb = tx * 4;

    // load Q tile once
    #pragma unroll
    for (int r = 0; r < 16; r++) {
        int idx = tid + r * 256;
        int ck = idx >> 4, mq = idx & 15;
        *(float4*)&Qs[ck * 64 + mq * 4] =
            *(const float4*)(f + ((size_t)ck << 12) + q0 + mq * 4);
    }

    float M[4], L[4];
    unsigned long long O2[4][8];
    #pragma unroll
    for (int i = 0; i < 4; i++) {
        M[i] = -1e30f; L[i] = 0.f;
        #pragma unroll
        for (int j = 0; j < 8; j++) O2[i][j] = 0ull;
    }

    for (int kb = 0; kb < NPIX / 64; kb++) {
        const int k0 = kb * 64;
        __syncthreads();   // prior iter finished reading Ks/Vs/Ps
        #pragma unroll
        for (int r = 0; r < 16; r++) {
            int idx = tid + r * 256;
            int ck = idx >> 4, mq = idx & 15;
            *(float4*)&Ks[ck * 64 + mq * 4] =
                *(const float4*)(f + ((size_t)ck << 12) + k0 + mq * 4);
        }
        #pragma unroll
        for (int r = 0; r < 16; r++) {
            int idx = tid + r * 256;
            int n = idx >> 6, cq = idx & 63;
            *(float4*)&Vs[n * 256 + cq * 4] =
                *(const float4*)(vt + (size_t)(k0 + n) * CV + cq * 4);
        }
        __syncthreads();

        // ---- S = Q K^T, f32x2: pairs along n ----
        unsigned long long s2[4][2] = {};
        #pragma unroll 8
        for (int ck = 0; ck < CK; ck++) {
            float4 a = *(float4*)&Qs[ck * 64 + mb];
            ulonglong2 k2 = *(const ulonglong2*)&Ks[ck * 64 + nb];
            unsigned long long a0 = f2pack(a.x, a.x);
            unsigned long long a1 = f2pack(a.y, a.y);
            unsigned long long a2 = f2pack(a.z, a.z);
            unsigned long long a3 = f2pack(a.w, a.w);
            f2fma(s2[0][0], a0, k2.x); f2fma(s2[0][1], a0, k2.y);
            f2fma(s2[1][0], a1, k2.x); f2fma(s2[1][1], a1, k2.y);
            f2fma(s2[2][0], a2, k2.x); f2fma(s2[2][1], a2, k2.y);
            f2fma(s2[3][0], a3, k2.x); f2fma(s2[3][1], a3, k2.y);
        }

        float s[4][4];
        #pragma unroll
        for (int i = 0; i < 4; i++) {
            float2 e0 = f2unpack(s2[i][0]);
            float2 e1 = f2unpack(s2[i][1]);
            s[i][0] = e0.x; s[i][1] = e0.y; s[i][2] = e1.x; s[i][3] = e1.y;
        }

        // ---- online softmax ----
        const float scale = 0.0625f;    // 1/sqrt(256)
        float rm[4];
        #pragma unroll
        for (int i = 0; i < 4; i++) {
            s[i][0] *= scale; s[i][1] *= scale; s[i][2] *= scale; s[i][3] *= scale;
            rm[i] = fmaxf(fmaxf(s[i][0], s[i][1]), fmaxf(s[i][2], s[i][3]));
        }
        #pragma unroll
        for (int off = 8; off > 0; off >>= 1)
            #pragma unroll
            for (int i = 0; i < 4; i++)
                rm[i] = fmaxf(rm[i], __shfl_xor_sync(0xffffffffu, rm[i], off));

        float c[4], rs[4];
        #pragma unroll
        for (int i = 0; i < 4; i++) {
            float mn = fmaxf(M[i], rm[i]);
            c[i] = __expf(M[i] - mn);
            M[i] = mn;
            rs[i] = 0.f;
        }
        #pragma unroll
        for (int i = 0; i < 4; i++)
            #pragma unroll
            for (int j = 0; j < 4; j++) {
                float p = __expf(s[i][j] - M[i]);
                Ps[(nb + j) * PS_LD + mb + i] = p;
                rs[i] += p;
            }
        #pragma unroll
        for (int off = 8; off > 0; off >>= 1)
            #pragma unroll
            for (int i = 0; i < 4; i++)
                rs[i] += __shfl_xor_sync(0xffffffffu, rs[i], off);
        #pragma unroll
        for (int i = 0; i < 4; i++) {
            L[i] = L[i] * c[i] + rs[i];
            unsigned long long cd = f2pack(c[i], c[i]);
            #pragma unroll
            for (int j = 0; j < 8; j++) f2mul(O2[i][j], cd);
        }
        __syncthreads();

        // ---- O += P V  (f32x2: pairs along cv) ----
        #pragma unroll 4
        for (int n = 0; n < 64; n++) {
            unsigned long long p0 = f2pack(Ps[n * PS_LD + mb + 0], Ps[n * PS_LD + mb + 0]);
            unsigned long long p1 = f2pack(Ps[n * PS_LD + mb + 1], Ps[n * PS_LD + mb + 1]);
            unsigned long long p2 = f2pack(Ps[n * PS_LD + mb + 2], Ps[n * PS_LD + mb + 2]);
            unsigned long long p3 = f2pack(Ps[n * PS_LD + mb + 3], Ps[n * PS_LD + mb + 3]);
            #pragma unroll
            for (int j = 0; j < 4; j++) {
                ulonglong2 v2 = *(const ulonglong2*)&Vs[n * 256 + tx * 4 + j * 64];
                f2fma(O2[0][j*2+0], p0, v2.x); f2fma(O2[0][j*2+1], p0, v2.y);
                f2fma(O2[1][j*2+0], p1, v2.x); f2fma(O2[1][j*2+1], p1, v2.y);
                f2fma(O2[2][j*2+0], p2, v2.x); f2fma(O2[2][j*2+1], p2, v2.y);
                f2fma(O2[3][j*2+0], p3, v2.x); f2fma(O2[3][j*2+1], p3, v2.y);
            }
        }
    }

    // ---- write ctx [B,N,Cv] ----
    #pragma unroll
    for (int i = 0; i < 4; i++) {
        float inv = 1.0f / L[i];
        float* dst = g_ctx + ((size_t)b * NPIX + q0 + mb + i) * CV;
        #pragma unroll
        for (int j = 0; j < 4; j++) {
            float2 e0 = f2unpack(O2[i][j*2+0]);
            float2 e1 = f2unpack(O2[i][j*2+1]);
            float4 o4 = {e0.x*inv, e0.y*inv, e1.x*inv, e1.y*inv};
            *(float4*)(dst + tx * 4 + j * 64) = o4;
        }
    }
}

// =====================================================================
// Kernel 6: out[b,co,n] = sum_cv Ww[co,cv]*ctx[b,n,cv] + bw[co]
// =====================================================================
#define B_LD 132
__global__ void __launch_bounds__(256) gemm_out_kernel(
    const float* __restrict__ Ww, const float* __restrict__ bw,
    float* __restrict__ out)
{
    __shared__ __align__(16) float As[G_BK][A_LD];
    __shared__ __align__(16) float Bs[G_BK][B_LD];

    const int b  = blockIdx.z;
    const int o0 = blockIdx.y * G_BM;
    const int n0 = blockIdx.x * G_BN;
    const int tid = threadIdx.x;
    const int tx = tid & 15, ty = tid >> 4;

    unsigned long long acc2[8][4] = {};

    for (int c0 = 0; c0 < CV; c0 += G_BK) {
        #pragma unroll
        for (int r = 0; r < 2; r++) {
            int idx = tid + r * 256;
            int m  = idx >> 2;
            int kq = idx & 3;
            float4 v = *(const float4*)(Ww + (size_t)(o0 + m) * CV + c0 + kq * 4);
            As[kq*4+0][m] = v.x; As[kq*4+1][m] = v.y;
            As[kq*4+2][m] = v.z; As[kq*4+3][m] = v.w;
        }
        #pragma unroll
        for (int r = 0; r < 2; r++) {
            int idx = tid + r * 256;
            int n  = idx >> 2;
            int kq = idx & 3;
            float4 v = *(const float4*)(g_ctx + ((size_t)b * NPIX + n0 + n) * CV + c0 + kq * 4);
            Bs[kq*4+0][n] = v.x; Bs[kq*4+1][n] = v.y;
            Bs[kq*4+2][n] = v.z; Bs[kq*4+3][n] = v.w;
        }
        __syncthreads();
        #pragma unroll
        for (int k = 0; k < G_BK; k++) {
            float a[8];
            *(float4*)&a[0] = *(float4*)&As[k][ty*8];
            *(float4*)&a[4] = *(float4*)&As[k][ty*8+4];
            ulonglong2 b0 = *(const ulonglong2*)&Bs[k][tx*8];
            ulonglong2 b1 = *(const ulonglong2*)&Bs[k][tx*8+4];
            #pragma unroll
            for (int i = 0; i < 8; i++) {
                unsigned long long ad = f2pack(a[i], a[i]);
                f2fma(acc2[i][0], ad, b0.x);
                f2fma(acc2[i][1], ad, b0.y);
                f2fma(acc2[i][2], ad, b1.x);
                f2fma(acc2[i][3], ad, b1.y);
            }
        }
        __syncthreads();
    }

    #pragma unroll
    for (int i = 0; i < 8; i++) {
        int o = o0 + ty * 8 + i;
        float bi = bw[o];
        float* p = out + (((size_t)b * CO + o) << 12) + n0 + tx * 8;
        float2 e0 = f2unpack(acc2[i][0]), e1 = f2unpack(acc2[i][1]);
        float2 e2 = f2unpack(acc2[i][2]), e3 = f2unpack(acc2[i][3]);
        float4 v0 = {e0.x+bi, e0.y+bi, e1.x+bi, e1.y+bi};
        float4 v1 = {e2.x+bi, e2.y+bi, e3.x+bi, e3.y+bi};
        *(float4*)p       = v0;
        *(float4*)(p + 4) = v1;
    }
}

// =====================================================================
// launch
// =====================================================================
extern "C" void kernel_launch(void* const* d_in, const int* in_sizes, int n_in,
                              void* d_out, int out_size)
{
    const float* x     = (const float*)d_in[0];
    const float* Wk    = (const float*)d_in[1];
    const float* bk    = (const float*)d_in[2];
    const float* gamma = (const float*)d_in[3];
    const float* beta  = (const float*)d_in[4];
    const float* Wv    = (const float*)d_in[5];
    const float* bv    = (const float*)d_in[6];
    const float* Ww    = (const float*)d_in[7];
    const float* bw    = (const float*)d_in[8];

    float* out   = (float*)d_out;                        // [8,512,64,64]
    float* feat1 = out   + (size_t)B_ * CO * NPIX;       // [8,256,64,64]
    float* feat2 = feat1 + (size_t)B_ * CK * NPIX;       // [8,256,64,64]
    float* value = feat2 + (size_t)B_ * CK * NPIX;       // [8,256,64,64]

    cudaFuncSetAttribute(attn_kernel,
                         cudaFuncAttributeMaxDynamicSharedMemorySize, ATTN_SMEM);

    // 1) fused QK/V conv1x1 GEMM
    gemm_qkv_kernel<<<dim3(NPIX / G_BN, (CK + CV) / G_BM, B_), 256>>>(
        x, Wk, bk, Wv, bv, value);

    // 2) BN stats
    bn_stats_kernel<<<CK, 256>>>();

    // 3) BN normalize + ReLU -> feat (written twice)
    feat_kernel<<<(B_ * CK * NPIX) / (4 * 256), 256>>>(gamma, beta, feat1, feat2);

    // 4) transpose value -> [B,N,Cv]
    transpose_v_kernel<<<dim3(NPIX / 32, CV / 32, B_), dim3(32, 8)>>>(value);

    // 5) flash attention -> g_ctx [B,N,Cv]
    attn_kernel<<<dim3(NPIX / 64, B_), 256, ATTN_SMEM>>>(feat1);

    // 6) output conv1x1 GEMM
    gemm_out_kernel<<<dim3(NPIX / G_BN, CO / G_BM, B_), 256>>>(Ww, bw, out);
}

// round 17
// speedup vs baseline: 2.0365x; 2.0365x over previous
#include <cuda_runtime.h>
#include <cuda_bf16.h>
#include <cstdint>

// ---------------- problem constants ----------------
#define B_   8
#define C_   512
#define NPIX 4096          // H*W = 64*64
#define CK   256
#define CV   256
#define CO   512
#define EPS  1e-5f

// ---------------- scratch (device globals; no allocation allowed) ----------
__device__ float g_qk [B_ * CK * NPIX];   // conv-k output, pre-BN   [B,Ck,N]
__device__ float g_vT [B_ * NPIX * CV];   // value transposed (tf32) [B,N,Cv]
__device__ float g_ctx[B_ * NPIX * CV];   // attention output        [B,N,Cv]
__device__ float g_mean[CK];
__device__ float g_rstd[CK];

// ---------------- packed f32x2 helpers (for the conv GEMMs) ----------------
__device__ __forceinline__ unsigned long long f2pack(float lo, float hi) {
    unsigned long long r;
    asm("mov.b64 %0, {%1, %2};" : "=l"(r) : "f"(lo), "f"(hi));
    return r;
}
__device__ __forceinline__ void f2fma(unsigned long long& acc,
                                      unsigned long long a, unsigned long long b) {
    asm("fma.rn.f32x2 %0, %1, %2, %0;" : "+l"(acc) : "l"(a), "l"(b));
}
__device__ __forceinline__ float2 f2unpack(unsigned long long v) {
    float2 f;
    asm("mov.b64 {%0, %1}, %2;" : "=f"(f.x), "=f"(f.y) : "l"(v));
    return f;
}

// ---------------- tf32 helpers ----------------
__device__ __forceinline__ float tf32r(float x) {
    float y;
    asm("cvt.rna.tf32.f32 %0, %1;" : "=f"(y) : "f"(x));
    return y;
}
__device__ __forceinline__ void mma_tf32(float4& d,
        uint32_t a0, uint32_t a1, uint32_t a2, uint32_t a3,
        uint32_t b0, uint32_t b1) {
    asm volatile(
        "mma.sync.aligned.m16n8k8.row.col.f32.tf32.tf32.f32 "
        "{%0,%1,%2,%3}, {%4,%5,%6,%7}, {%8,%9}, {%0,%1,%2,%3};"
        : "+f"(d.x), "+f"(d.y), "+f"(d.z), "+f"(d.w)
        : "r"(a0), "r"(a1), "r"(a2), "r"(a3), "r"(b0), "r"(b1));
}

// =====================================================================
// Kernel 1: fused QKV 1x1 conv GEMM (f32x2 micro-kernel).
// =====================================================================
#define G_BM 128
#define G_BN 128
#define G_BK 16
#define A_LD 132

__global__ void __launch_bounds__(256) gemm_qkv_kernel(
    const float* __restrict__ x,
    const float* __restrict__ Wk, const float* __restrict__ bk,
    const float* __restrict__ Wv, const float* __restrict__ bv,
    float* __restrict__ value)
{
    __shared__ __align__(16) float As[G_BK][A_LD];
    __shared__ __align__(16) float Bs[G_BK][G_BN];

    const int b  = blockIdx.z;
    const int o0 = blockIdx.y * G_BM;
    const int n0 = blockIdx.x * G_BN;
    const int tid = threadIdx.x;
    const int tx = tid & 15, ty = tid >> 4;

    const bool is_k = (o0 < CK);
    const float* W    = is_k ? Wk : Wv;
    const float* bias = is_k ? bk : bv;
    float*       dst  = is_k ? g_qk : value;
    const int or0 = o0 & (CK - 1);

    unsigned long long acc2[8][4] = {};

    for (int c0 = 0; c0 < C_; c0 += G_BK) {
        #pragma unroll
        for (int r = 0; r < 2; r++) {
            int idx = tid + r * 256;
            int m  = idx >> 2;
            int kq = idx & 3;
            float4 v = *(const float4*)(W + (size_t)(or0 + m) * C_ + c0 + kq * 4);
            As[kq*4+0][m] = v.x; As[kq*4+1][m] = v.y;
            As[kq*4+2][m] = v.z; As[kq*4+3][m] = v.w;
        }
        #pragma unroll
        for (int r = 0; r < 2; r++) {
            int idx = tid + r * 256;
            int k  = idx >> 5;
            int nq = idx & 31;
            *(float4*)&Bs[k][nq*4] =
                *(const float4*)(x + (((size_t)b * C_ + c0 + k) << 12) + n0 + nq * 4);
        }
        __syncthreads();
        #pragma unroll
        for (int k = 0; k < G_BK; k++) {
            float a[8];
            *(float4*)&a[0] = *(float4*)&As[k][ty*8];
            *(float4*)&a[4] = *(float4*)&As[k][ty*8+4];
            ulonglong2 b0 = *(const ulonglong2*)&Bs[k][tx*8];
            ulonglong2 b1 = *(const ulonglong2*)&Bs[k][tx*8+4];
            #pragma unroll
            for (int i = 0; i < 8; i++) {
                unsigned long long ad = f2pack(a[i], a[i]);
                f2fma(acc2[i][0], ad, b0.x);
                f2fma(acc2[i][1], ad, b0.y);
                f2fma(acc2[i][2], ad, b1.x);
                f2fma(acc2[i][3], ad, b1.y);
            }
        }
        __syncthreads();
    }

    #pragma unroll
    for (int i = 0; i < 8; i++) {
        int o = or0 + ty * 8 + i;
        float bi = bias[o];
        float* p = dst + (((size_t)b * CK + o) << 12) + n0 + tx * 8;
        float2 e0 = f2unpack(acc2[i][0]), e1 = f2unpack(acc2[i][1]);
        float2 e2 = f2unpack(acc2[i][2]), e3 = f2unpack(acc2[i][3]);
        float4 v0 = {e0.x+bi, e0.y+bi, e1.x+bi, e1.y+bi};
        float4 v1 = {e2.x+bi, e2.y+bi, e3.x+bi, e3.y+bi};
        *(float4*)p       = v0;
        *(float4*)(p + 4) = v1;
    }
}

// =====================================================================
// Kernel 2: BN training statistics per channel over (B, N) = 32768 vals.
// =====================================================================
__global__ void __launch_bounds__(256) bn_stats_kernel()
{
    const int ck = blockIdx.x;
    float s = 0.f, s2 = 0.f;
    for (int i = threadIdx.x; i < B_ * NPIX; i += 256) {
        int b = i >> 12;
        int n = i & (NPIX - 1);
        float v = g_qk[(((size_t)b * CK + ck) << 12) + n];
        s += v; s2 += v * v;
    }
    #pragma unroll
    for (int off = 16; off > 0; off >>= 1) {
        s  += __shfl_xor_sync(0xffffffffu, s,  off);
        s2 += __shfl_xor_sync(0xffffffffu, s2, off);
    }
    __shared__ float sb[16];
    int w = threadIdx.x >> 5;
    if ((threadIdx.x & 31) == 0) { sb[w] = s; sb[8 + w] = s2; }
    __syncthreads();
    if (threadIdx.x == 0) {
        float S = 0.f, S2 = 0.f;
        #pragma unroll
        for (int i = 0; i < 8; i++) { S += sb[i]; S2 += sb[8 + i]; }
        const float invN = 1.f / (float)(B_ * NPIX);
        float mean = S * invN;
        float var  = S2 * invN - mean * mean;
        g_mean[ck] = mean;
        g_rstd[ck] = rsqrtf(var + EPS);
    }
}

// =====================================================================
// Kernel 3: feat = relu((qk-mean)*rstd*gamma + beta) -> two d_out slots
// =====================================================================
__global__ void __launch_bounds__(256) feat_kernel(
    const float* __restrict__ gamma, const float* __restrict__ beta,
    float* __restrict__ feat1, float* __restrict__ feat2)
{
    int i4 = blockIdx.x * 256 + threadIdx.x;
    int e  = i4 * 4;
    int ck = (e >> 12) & (CK - 1);
    float mu = g_mean[ck], r = g_rstd[ck];
    float sc = r * gamma[ck], be = beta[ck];
    float4 v = *(const float4*)(g_qk + e);
    float4 f;
    f.x = fmaxf(0.f, (v.x - mu) * sc + be);
    f.y = fmaxf(0.f, (v.y - mu) * sc + be);
    f.z = fmaxf(0.f, (v.z - mu) * sc + be);
    f.w = fmaxf(0.f, (v.w - mu) * sc + be);
    *(float4*)(feat1 + e) = f;
    *(float4*)(feat2 + e) = f;
}

// =====================================================================
// Kernel 4: value [B,Cv,N] -> vT [B,N,Cv], rounded to tf32 for attention.
// =====================================================================
__global__ void __launch_bounds__(256) transpose_v_kernel(const float* __restrict__ value)
{
    __shared__ float t[32][33];
    const int b  = blockIdx.z;
    const int n0 = blockIdx.x * 32;
    const int c0 = blockIdx.y * 32;
    #pragma unroll
    for (int r = 0; r < 4; r++) {
        int row = c0 + threadIdx.y + r * 8;
        t[threadIdx.y + r*8][threadIdx.x] =
            value[(((size_t)b * CV + row) << 12) + n0 + threadIdx.x];
    }
    __syncthreads();
    #pragma unroll
    for (int r = 0; r < 4; r++) {
        int row = n0 + threadIdx.y + r * 8;
        g_vT[((size_t)b * NPIX + row) * CV + c0 + threadIdx.x] =
            tf32r(t[threadIdx.x][threadIdx.y + r*8]);
    }
}

// =====================================================================
// Kernel 5: flash attention with tf32 mma.sync tensor cores.
//   BM=64 q rows per CTA, BN=64 k block, D=256. 256 threads = 8 warps.
//   Warp grid: 4 (m) x 2 (n / cv-half). O accumulators in registers.
//   smem LDs chosen so fragment LDS.32 hit 32 distinct banks:
//     Q  m-major  [64][260]   (260 % 32 == 4)
//     K  ck-major [256][72]   (72  % 32 == 8)
//     V  n-major  [64][264]   (264 % 32 == 8)
//     P  m-major  [64][68]    (68  % 32 == 4)
// =====================================================================
#define QLD 260
#define KLD 72
#define VLD 264
#define PLD 68
#define OFF_Q 0
#define OFF_K (OFF_Q + 64 * QLD)          // 16640
#define OFF_V (OFF_K + 256 * KLD)         // 35072
#define OFF_P (OFF_V + 64 * VLD)          // 51968
#define OFF_M (OFF_P + 64 * PLD)          // 56320
#define OFF_L (OFF_M + 64)
#define OFF_C (OFF_L + 64)
#define ATTN_FLOATS (OFF_C + 64)          // 56512
#define ATTN_SMEM (ATTN_FLOATS * 4)       // 226048 B

__global__ void __launch_bounds__(256, 1) attn_kernel(
    const float* __restrict__ feat)   // [B,Ck,N] (d_out feat1 slot, fp32)
{
    extern __shared__ __align__(16) float sm[];
    float* Qs = sm + OFF_Q;
    float* Ks = sm + OFF_K;
    float* Vs = sm + OFF_V;
    float* Ps = sm + OFF_P;
    float* Mrow = sm + OFF_M;
    float* Lrow = sm + OFF_L;
    float* Crow = sm + OFF_C;

    const int b  = blockIdx.y;
    const int q0 = blockIdx.x * 64;
    const float* f  = feat + (size_t)b * CK * NPIX;
    const float* vt = g_vT + (size_t)b * NPIX * CV;

    const int tid  = threadIdx.x;
    const int lane = tid & 31;
    const int lr   = lane >> 2;          // 0..7
    const int lc   = lane & 3;           // 0..3
    const int w    = tid >> 5;
    const int m0w  = (w & 3) * 16;       // warp m offset
    const int wn   = w >> 2;             // 0..1
    const int n0w  = wn * 32;            // QK: n offset
    const int cv0w = wn * 128;           // PV: cv offset

    // --- Q tile: load, tf32-round, transpose to m-major (once) ---
    #pragma unroll
    for (int r = 0; r < 16; r++) {
        int idx = tid + r * 256;
        int ck = idx >> 4, mq = idx & 15;
        float4 v = *(const float4*)(f + ((size_t)ck << 12) + q0 + mq * 4);
        Qs[(mq*4+0) * QLD + ck] = tf32r(v.x);
        Qs[(mq*4+1) * QLD + ck] = tf32r(v.y);
        Qs[(mq*4+2) * QLD + ck] = tf32r(v.z);
        Qs[(mq*4+3) * QLD + ck] = tf32r(v.w);
    }
    if (tid < 64) { Mrow[tid] = -1e30f; Lrow[tid] = 0.f; }

    float4 O[16];
    #pragma unroll
    for (int ch = 0; ch < 16; ch++) O[ch] = make_float4(0.f, 0.f, 0.f, 0.f);

    const float scale = 0.0625f;   // 1/sqrt(256)

    for (int kb = 0; kb < NPIX / 64; kb++) {
        const int k0 = kb * 64;
        __syncthreads();   // prior iter done reading Ks/Vs/Ps

        // --- load K tile (tf32-round) and V tile ---
        #pragma unroll
        for (int r = 0; r < 16; r++) {
            int idx = tid + r * 256;
            int ck = idx >> 4, nq = idx & 15;
            float4 v = *(const float4*)(f + ((size_t)ck << 12) + k0 + nq * 4);
            float4 t = {tf32r(v.x), tf32r(v.y), tf32r(v.z), tf32r(v.w)};
            *(float4*)&Ks[ck * KLD + nq * 4] = t;
        }
        #pragma unroll
        for (int r = 0; r < 16; r++) {
            int idx = tid + r * 256;
            int n = idx >> 6, cq = idx & 63;
            *(float4*)&Vs[n * VLD + cq * 4] =
                *(const float4*)(vt + (size_t)(k0 + n) * CV + cq * 4);
        }
        __syncthreads();

        // --- S = Q K^T on tensor cores (warp tile 16x32) ---
        float4 S[4] = {};
        {
            const float* qa = Qs + (m0w + lr) * QLD + lc;
            const float* kp = Ks + lc * KLD + n0w + lr;
            #pragma unroll 4
            for (int k8 = 0; k8 < 32; k8++) {
                const float* q_ = qa + k8 * 8;
                uint32_t a0 = __float_as_uint(q_[0]);
                uint32_t a1 = __float_as_uint(q_[8 * QLD]);
                uint32_t a2 = __float_as_uint(q_[4]);
                uint32_t a3 = __float_as_uint(q_[8 * QLD + 4]);
                const float* k_ = kp + k8 * 8 * KLD;
                #pragma unroll
                for (int c = 0; c < 4; c++) {
                    uint32_t b0 = __float_as_uint(k_[c * 8]);
                    uint32_t b1 = __float_as_uint(k_[4 * KLD + c * 8]);
                    mma_tf32(S[c], a0, a1, a2, a3, b0, b1);
                }
            }
        }
        // write raw S to Ps (m-major)
        {
            float* p0 = Ps + (m0w + lr) * PLD + n0w + 2 * lc;
            float* p1 = p0 + 8 * PLD;
            #pragma unroll
            for (int c = 0; c < 4; c++) {
                *(float2*)(p0 + c * 8) = make_float2(S[c].x, S[c].y);
                *(float2*)(p1 + c * 8) = make_float2(S[c].z, S[c].w);
            }
        }
        __syncthreads();

        // --- softmax pass over Ps rows (4 threads per row) ---
        {
            const int row = tid >> 2, sub = tid & 3;
            float* pr = Ps + row * PLD + sub * 16;
            float4 sv[4];
            #pragma unroll
            for (int j = 0; j < 4; j++) sv[j] = *(float4*)(pr + j * 4);
            float vmax = -1e30f;
            #pragma unroll
            for (int j = 0; j < 4; j++)
                vmax = fmaxf(vmax, fmaxf(fmaxf(sv[j].x, sv[j].y), fmaxf(sv[j].z, sv[j].w)));
            vmax = fmaxf(vmax, __shfl_xor_sync(0xffffffffu, vmax, 1));
            vmax = fmaxf(vmax, __shfl_xor_sync(0xffffffffu, vmax, 2));
            float Mold = Mrow[row];
            float Mnew = fmaxf(Mold, vmax * scale);
            float c    = __expf(Mold - Mnew);
            float rs = 0.f;
            #pragma unroll
            for (int j = 0; j < 4; j++) {
                sv[j].x = __expf(sv[j].x * scale - Mnew);
                sv[j].y = __expf(sv[j].y * scale - Mnew);
                sv[j].z = __expf(sv[j].z * scale - Mnew);
                sv[j].w = __expf(sv[j].w * scale - Mnew);
                rs += sv[j].x + sv[j].y + sv[j].z + sv[j].w;
                float4 t = {tf32r(sv[j].x), tf32r(sv[j].y), tf32r(sv[j].z), tf32r(sv[j].w)};
                *(float4*)(pr + j * 4) = t;
            }
            rs += __shfl_xor_sync(0xffffffffu, rs, 1);
            rs += __shfl_xor_sync(0xffffffffu, rs, 2);
            if (sub == 0) {
                Lrow[row] = Lrow[row] * c + rs;
                Crow[row] = c;
                Mrow[row] = Mnew;
            }
        }
        __syncthreads();

        // --- rescale O, then O += P V on tensor cores (warp tile 16x128) ---
        {
            float c0 = Crow[m0w + lr];
            float c1 = Crow[m0w + lr + 8];
            #pragma unroll
            for (int ch = 0; ch < 16; ch++) {
                O[ch].x *= c0; O[ch].y *= c0;
                O[ch].z *= c1; O[ch].w *= c1;
            }
            const float* pa = Ps + (m0w + lr) * PLD + lc;
            const float* vb = Vs + lc * VLD + cv0w + lr;
            #pragma unroll 2
            for (int k8 = 0; k8 < 8; k8++) {
                const float* p_ = pa + k8 * 8;
                uint32_t a0 = __float_as_uint(p_[0]);
                uint32_t a1 = __float_as_uint(p_[8 * PLD]);
                uint32_t a2 = __float_as_uint(p_[4]);
                uint32_t a3 = __float_as_uint(p_[8 * PLD + 4]);
                const float* v_ = vb + k8 * 8 * VLD;
                #pragma unroll
                for (int ch = 0; ch < 16; ch++) {
                    uint32_t b0 = __float_as_uint(v_[ch * 8]);
                    uint32_t b1 = __float_as_uint(v_[4 * VLD + ch * 8]);
                    mma_tf32(O[ch], a0, a1, a2, a3, b0, b1);
                }
            }
        }
    }

    __syncthreads();
    // --- epilogue: ctx[b, q0+m, cv] = O / L ---
    {
        const int r0 = m0w + lr, r1 = r0 + 8;
        float i0 = 1.0f / Lrow[r0];
        float i1 = 1.0f / Lrow[r1];
        float* base0 = g_ctx + ((size_t)b * NPIX + q0 + r0) * CV + cv0w + 2 * lc;
        float* base1 = g_ctx + ((size_t)b * NPIX + q0 + r1) * CV + cv0w + 2 * lc;
        #pragma unroll
        for (int ch = 0; ch < 16; ch++) {
            *(float2*)(base0 + ch * 8) = make_float2(O[ch].x * i0, O[ch].y * i0);
            *(float2*)(base1 + ch * 8) = make_float2(O[ch].z * i1, O[ch].w * i1);
        }
    }
}

// =====================================================================
// Kernel 6: out[b,co,n] = sum_cv Ww[co,cv]*ctx[b,n,cv] + bw[co]
// =====================================================================
#define B_LD 132
__global__ void __launch_bounds__(256) gemm_out_kernel(
    const float* __restrict__ Ww, const float* __restrict__ bw,
    float* __restrict__ out)
{
    __shared__ __align__(16) float As[G_BK][A_LD];
    __shared__ __align__(16) float Bs[G_BK][B_LD];

    const int b  = blockIdx.z;
    const int o0 = blockIdx.y * G_BM;
    const int n0 = blockIdx.x * G_BN;
    const int tid = threadIdx.x;
    const int tx = tid & 15, ty = tid >> 4;

    unsigned long long acc2[8][4] = {};

    for (int c0 = 0; c0 < CV; c0 += G_BK) {
        #pragma unroll
        for (int r = 0; r < 2; r++) {
            int idx = tid + r * 256;
            int m  = idx >> 2;
            int kq = idx & 3;
            float4 v = *(const float4*)(Ww + (size_t)(o0 + m) * CV + c0 + kq * 4);
            As[kq*4+0][m] = v.x; As[kq*4+1][m] = v.y;
            As[kq*4+2][m] = v.z; As[kq*4+3][m] = v.w;
        }
        #pragma unroll
        for (int r = 0; r < 2; r++) {
            int idx = tid + r * 256;
            int n  = idx >> 2;
            int kq = idx & 3;
            float4 v = *(const float4*)(g_ctx + ((size_t)b * NPIX + n0 + n) * CV + c0 + kq * 4);
            Bs[kq*4+0][n] = v.x; Bs[kq*4+1][n] = v.y;
            Bs[kq*4+2][n] = v.z; Bs[kq*4+3][n] = v.w;
        }
        __syncthreads();
        #pragma unroll
        for (int k = 0; k < G_BK; k++) {
            float a[8];
            *(float4*)&a[0] = *(float4*)&As[k][ty*8];
            *(float4*)&a[4] = *(float4*)&As[k][ty*8+4];
            ulonglong2 b0 = *(const ulonglong2*)&Bs[k][tx*8];
            ulonglong2 b1 = *(const ulonglong2*)&Bs[k][tx*8+4];
            #pragma unroll
            for (int i = 0; i < 8; i++) {
                unsigned long long ad = f2pack(a[i], a[i]);
                f2fma(acc2[i][0], ad, b0.x);
                f2fma(acc2[i][1], ad, b0.y);
                f2fma(acc2[i][2], ad, b1.x);
                f2fma(acc2[i][3], ad, b1.y);
            }
        }
        __syncthreads();
    }

    #pragma unroll
    for (int i = 0; i < 8; i++) {
        int o = o0 + ty * 8 + i;
        float bi = bw[o];
        float* p = out + (((size_t)b * CO + o) << 12) + n0 + tx * 8;
        float2 e0 = f2unpack(acc2[i][0]), e1 = f2unpack(acc2[i][1]);
        float2 e2 = f2unpack(acc2[i][2]), e3 = f2unpack(acc2[i][3]);
        float4 v0 = {e0.x+bi, e0.y+bi, e1.x+bi, e1.y+bi};
        float4 v1 = {e2.x+bi, e2.y+bi, e3.x+bi, e3.y+bi};
        *(float4*)p       = v0;
        *(float4*)(p + 4) = v1;
    }
}

// =====================================================================
// launch
// =====================================================================
extern "C" void kernel_launch(void* const* d_in, const int* in_sizes, int n_in,
                              void* d_out, int out_size)
{
    const float* x     = (const float*)d_in[0];
    const float* Wk    = (const float*)d_in[1];
    const float* bk    = (const float*)d_in[2];
    const float* gamma = (const float*)d_in[3];
    const float* beta  = (const float*)d_in[4];
    const float* Wv    = (const float*)d_in[5];
    const float* bv    = (const float*)d_in[6];
    const float* Ww    = (const float*)d_in[7];
    const float* bw    = (const float*)d_in[8];

    float* out   = (float*)d_out;                        // [8,512,64,64]
    float* feat1 = out   + (size_t)B_ * CO * NPIX;       // [8,256,64,64]
    float* feat2 = feat1 + (size_t)B_ * CK * NPIX;       // [8,256,64,64]
    float* value = feat2 + (size_t)B_ * CK * NPIX;       // [8,256,64,64]

    cudaFuncSetAttribute(attn_kernel,
                         cudaFuncAttributeMaxDynamicSharedMemorySize, ATTN_SMEM);

    // 1) fused QK/V conv1x1 GEMM
    gemm_qkv_kernel<<<dim3(NPIX / G_BN, (CK + CV) / G_BM, B_), 256>>>(
        x, Wk, bk, Wv, bv, value);

    // 2) BN stats
    bn_stats_kernel<<<CK, 256>>>();

    // 3) BN normalize + ReLU -> feat (written twice)
    feat_kernel<<<(B_ * CK * NPIX) / (4 * 256), 256>>>(gamma, beta, feat1, feat2);

    // 4) transpose value -> [B,N,Cv] (tf32-rounded)
    transpose_v_kernel<<<dim3(NPIX / 32, CV / 32, B_), dim3(32, 8)>>>(value);

    // 5) flash attention (tf32 tensor cores) -> g_ctx [B,N,Cv]
    attn_kernel<<<dim3(NPIX / 64, B_), 256, ATTN_SMEM>>>(feat1);

    // 6) output conv1x1 GEMM
    gemm_out_kernel<<<dim3(NPIX / G_BN, CO / G_BM, B_), 256>>>(Ww, bw, out);
}